// round 10
// baseline (speedup 1.0000x reference)
#include <cuda_runtime.h>

#define N_GRID 64
#define N1 65
#define B_PTS 262144
#define W_FEAT 256

// Region = 4x2x4 cells (x,y,z) -> 16*32*16 = 8192 regions, ~32 pts each.
// Rows needed per region: 5*3*5 = 75 rows of 256 floats = 75 KB (smem-staged).
#define NREG 8192
#define NROWS 75
#define SMEM_BYTES (NROWS * 64 * 16)   // 75 rows * 64 float4 = 76800 B
#define INTERP_BLOCK 512

// Scratch (device globals: allocation-free per harness rules)
__device__ int    g_hist[NREG];
__device__ int    g_off[NREG];          // scatter cursor (mutated)
__device__ int    g_start[NREG + 1];    // immutable bin starts
__device__ int    g_regid[B_PTS];
__device__ float4 g_sorted[B_PTS];      // (px,py,pz, bitcast(pt))

// ---------------------------------------------------------------------------
// K0: zero histogram (every call, for graph-replay determinism)
__global__ void k_zero_hist() {
    g_hist[blockIdx.x * blockDim.x + threadIdx.x] = 0;
}

// K1: region id per point + histogram
__global__ void k_cells(const float* __restrict__ x) {
    int pt = blockIdx.x * blockDim.x + threadIdx.x;
    if (pt >= B_PTS) return;
    float rx = (x[3 * pt + 0] + 1.0f) * 32.0f;
    float ry = (x[3 * pt + 1] + 1.0f) * 32.0f;
    float rz = (x[3 * pt + 2] + 1.0f) * 32.0f;
    int ix = min(max((int)floorf(rx), 0), N_GRID - 1);
    int iy = min(max((int)floorf(ry), 0), N_GRID - 1);
    int iz = min(max((int)floorf(rz), 0), N_GRID - 1);
    int reg = (((ix >> 2) << 5 | (iy >> 1)) << 4) | (iz >> 2);
    g_regid[pt] = reg;
    atomicAdd(&g_hist[reg], 1);
}

// K2: exclusive scan over 8192 bins — ONE block, 1024 threads x 8 items.
__global__ __launch_bounds__(1024) void k_scan() {
    int tid = threadIdx.x;
    int lane = tid & 31, wid = tid >> 5;
    int base = tid * 8;

    int v[8];
    int run = 0;
#pragma unroll
    for (int i = 0; i < 8; i++) {
        int h = g_hist[base + i];
        v[i] = run;
        run += h;
    }
    int inc = run;
#pragma unroll
    for (int d = 1; d < 32; d <<= 1) {
        int t = __shfl_up_sync(0xffffffffu, inc, d);
        if (lane >= d) inc += t;
    }
    __shared__ int wsum[32];
    __shared__ int woff[32];
    if (lane == 31) wsum[wid] = inc;
    __syncthreads();
    if (tid == 0) {
        int s = 0;
#pragma unroll
        for (int w = 0; w < 32; w++) { woff[w] = s; s += wsum[w]; }
    }
    __syncthreads();
    int ex = inc - run + woff[wid];
#pragma unroll
    for (int i = 0; i < 8; i++) {
        g_off[base + i]   = ex + v[i];
        g_start[base + i] = ex + v[i];
    }
    if (tid == 1023) g_start[NREG] = B_PTS;
}

// K3: scatter points into region-sorted order (intra-region order arbitrary —
// harmless now, the interp kernel reads corners from smem)
__global__ void k_scatter(const float* __restrict__ x) {
    int pt = blockIdx.x * blockDim.x + threadIdx.x;
    if (pt >= B_PTS) return;
    int r = g_regid[pt];
    int pos = atomicAdd(&g_off[r], 1);
    float4 s;
    s.x = x[3 * pt + 0];
    s.y = x[3 * pt + 1];
    s.z = x[3 * pt + 2];
    s.w = __int_as_float(pt);
    g_sorted[pos] = s;
}

// ---------------------------------------------------------------------------
// K4: one block per region. Stage the region's 75 feature rows in smem
// (each row fetched from L2 exactly once per block, coalesced), then gather
// all of the region's points from smem at the full 128 B/cyc LDS rate.
__global__ __launch_bounds__(INTERP_BLOCK) void k_interp(
    const float* __restrict__ grid_value,
    const float* __restrict__ grid_feature,
    float* __restrict__ out,
    float* __restrict__ feat)
{
    extern __shared__ float4 s_rows[];   // [75][64]

    int r = blockIdx.x;
    int pstart = g_start[r];
    int pend   = g_start[r + 1];
    if (pstart == pend) return;

    int tid = threadIdx.x;
    // region origin in cells: reg = ((ix>>2)<<5 | (iy>>1))<<4 | (iz>>2)
    int X0 = (r >> 9) << 2;
    int Y0 = ((r >> 4) & 31) << 1;
    int Z0 = (r & 15) << 2;

    // ---- fill: 75 rows x 64 float4, coalesced (1 KB contiguous per row)
    for (int i = tid; i < NROWS * 64; i += INTERP_BLOCK) {
        int row  = i >> 6;
        int lane = i & 63;
        int dz = row % 5;
        int t  = row / 5;
        int dy = t % 3;
        int dx = t / 3;
        int g = ((X0 + dx) * N1 + (Y0 + dy)) * N1 + (Z0 + dz);
        s_rows[i] = __ldg(reinterpret_cast<const float4*>(grid_feature) +
                          (size_t)g * 64 + lane);
    }
    __syncthreads();

    // ---- gather: 8 subgroups of 64 threads, one point each per iteration
    int sub  = tid >> 6;     // 0..7
    int lane = tid & 63;

    for (int p = pstart + sub; p < pend; p += INTERP_BLOCK / 64) {
        float4 s = g_sorted[p];
        int pt = __float_as_int(s.w);

        float rx = (s.x + 1.0f) * 32.0f;
        float ry = (s.y + 1.0f) * 32.0f;
        float rz = (s.z + 1.0f) * 32.0f;

        bool valid = (rx >= 0.0f) && (rx <= 64.0f) &&
                     (ry >= 0.0f) && (ry <= 64.0f) &&
                     (rz >= 0.0f) && (rz <= 64.0f);

        int ix = min(max((int)floorf(rx), 0), N_GRID - 1);
        int iy = min(max((int)floorf(ry), 0), N_GRID - 1);
        int iz = min(max((int)floorf(rz), 0), N_GRID - 1);

        float tx = rx - (float)ix;
        float ty = ry - (float)iy;
        float tz = rz - (float)iz;
        float ux = 1.0f - tx, uy = 1.0f - ty, uz = 1.0f - tz;

        float w[8];
        w[0] = ux * uy * uz;
        w[1] = ux * uy * tz;
        w[2] = ux * ty * uz;
        w[3] = ux * ty * tz;
        w[4] = tx * uy * uz;
        w[5] = tx * uy * tz;
        w[6] = tx * ty * uz;
        w[7] = tx * ty * tz;

        int dx = ix - X0, dy = iy - Y0, dz = iz - Z0;   // dx,dz in [0,4), dy in [0,2)
        int sb = (dx * 3 + dy) * 5 + dz;                 // smem row of corner 000
        // corner smem rows: +oz, +5*oy, +15*ox
        int srow[8];
        srow[0] = sb;
        srow[1] = sb + 1;
        srow[2] = sb + 5;
        srow[3] = sb + 6;
        srow[4] = sb + 15;
        srow[5] = sb + 16;
        srow[6] = sb + 20;
        srow[7] = sb + 21;

        float4 acc = make_float4(0.f, 0.f, 0.f, 0.f);
#pragma unroll
        for (int c = 0; c < 8; c++) {
            float4 v = s_rows[srow[c] * 64 + lane];
            float wc = w[c];
            acc.x = fmaf(wc, v.x, acc.x);
            acc.y = fmaf(wc, v.y, acc.y);
            acc.z = fmaf(wc, v.z, acc.z);
            acc.w = fmaf(wc, v.w, acc.w);
        }

        if (!valid) acc = make_float4(0.f, 0.f, 0.f, 0.f);
        __stcs(reinterpret_cast<float4*>(feat + (size_t)pt * W_FEAT) + lane, acc);

        if (lane == 0) {
            int gb = ((X0 + dx) * N1 + (Y0 + dy)) * N1 + (Z0 + dz);
            float sv = 0.0f;
            sv = fmaf(w[0], __ldg(&grid_value[gb]), sv);
            sv = fmaf(w[1], __ldg(&grid_value[gb + 1]), sv);
            sv = fmaf(w[2], __ldg(&grid_value[gb + N1]), sv);
            sv = fmaf(w[3], __ldg(&grid_value[gb + N1 + 1]), sv);
            sv = fmaf(w[4], __ldg(&grid_value[gb + N1 * N1]), sv);
            sv = fmaf(w[5], __ldg(&grid_value[gb + N1 * N1 + 1]), sv);
            sv = fmaf(w[6], __ldg(&grid_value[gb + N1 * N1 + N1]), sv);
            sv = fmaf(w[7], __ldg(&grid_value[gb + N1 * N1 + N1 + 1]), sv);
            __stcs(&out[pt], valid ? sv : 0.0f);
        }
    }
}

// ---------------------------------------------------------------------------
extern "C" void kernel_launch(void* const* d_in, const int* in_sizes, int n_in,
                              void* d_out, int out_size)
{
    const float* x            = (const float*)d_in[0];
    const float* grid_value   = (const float*)d_in[1];
    const float* grid_feature = (const float*)d_in[2];
    float* out  = (float*)d_out;          // [B,1]
    float* feat = (float*)d_out + B_PTS;  // [B,256]

    // idempotent; needed for 75 KB dynamic smem
    cudaFuncSetAttribute(k_interp, cudaFuncAttributeMaxDynamicSharedMemorySize,
                         SMEM_BYTES);

    k_zero_hist<<<NREG / 1024, 1024>>>();
    k_cells<<<B_PTS / 256, 256>>>(x);
    k_scan<<<1, 1024>>>();
    k_scatter<<<B_PTS / 256, 256>>>(x);

    k_interp<<<NREG, INTERP_BLOCK, SMEM_BYTES>>>(grid_value, grid_feature, out, feat);
}